// round 2
// baseline (speedup 1.0000x reference)
#include <cuda_runtime.h>

#define DD   256
#define E2   512
#define NT   128
#define NF   128
#define NBN  16
#define SROW 516
#define EPS  1e-5f

typedef unsigned long long u64;

// ---------------- packed f32x2 helpers (Blackwell 2xFP32) ------------------
__device__ __forceinline__ u64 add2(u64 a, u64 b) {
    u64 d; asm("add.rn.f32x2 %0,%1,%2;" : "=l"(d) : "l"(a), "l"(b)); return d;
}
__device__ __forceinline__ u64 fma2(u64 a, u64 b, u64 c) {
    u64 d; asm("fma.rn.f32x2 %0,%1,%2,%3;" : "=l"(d) : "l"(a), "l"(b), "l"(c)); return d;
}
__device__ __forceinline__ u64 relu2(u64 a) {
    u64 d;
    asm("{\n\t.reg .f32 l,h;\n\tmov.b64 {l,h}, %1;\n\t"
        "max.f32 l, l, 0f00000000;\n\tmax.f32 h, h, 0f00000000;\n\t"
        "mov.b64 %0, {l,h};\n\t}" : "=l"(d) : "l"(a));
    return d;
}
__device__ __forceinline__ float sum2(u64 a) {
    float l, h; asm("mov.b64 {%0,%1}, %2;" : "=f"(l), "=f"(h) : "l"(a)); return l + h;
}
__device__ __forceinline__ u64 pack2(float v) {
    u64 d; asm("mov.b64 %0, {%1,%1};" : "=l"(d) : "f"(v)); return d;
}

// ---------------- scratch (device globals; no allocation allowed) ----------
__device__ float g_cx[NBN * DD];
__device__ float g_ct[NT * DD];
__device__ float g_cf[NF * DD];
__device__ float g_qx[NBN];
__device__ float g_qt[NT];
__device__ float g_qf[NF];
__device__ float g_dxt[NBN * NT];
__device__ float g_dxf[NBN * NF];
__device__ float g_dtf[NT * NF];
__device__ float g_ux[NBN * E2];
__device__ float g_ut[NT * E2];
__device__ float g_uf[NF * E2];
__device__ float g_c[E2];

// ---------------- P1: center each embedding row, store centered + sq-norm --
__global__ void k_center(const float* __restrict__ x,
                         const float* __restrict__ t_emb,
                         const float* __restrict__ f_emb) {
    __shared__ float red[8];
    __shared__ float s_mu;
    int r = blockIdx.x;
    const float* src;
    float* dst;
    float* q;
    if (r < 16)       { src = x + r * DD;            dst = g_cx + r * DD;        q = g_qx + r; }
    else if (r < 144) { int i = r - 16;  src = t_emb + i * DD; dst = g_ct + i * DD; q = g_qt + i; }
    else              { int i = r - 144; src = f_emb + i * DD; dst = g_cf + i * DD; q = g_qf + i; }

    int tid = threadIdx.x;
    float v = src[tid];

    float s = v;
    #pragma unroll
    for (int o = 16; o; o >>= 1) s += __shfl_xor_sync(0xffffffffu, s, o);
    if ((tid & 31) == 0) red[tid >> 5] = s;
    __syncthreads();
    if (tid == 0) {
        float tot = 0.f;
        #pragma unroll
        for (int i = 0; i < 8; i++) tot += red[i];
        s_mu = tot * (1.0f / DD);
    }
    __syncthreads();

    float c = v - s_mu;
    dst[tid] = c;

    s = c * c;
    #pragma unroll
    for (int o = 16; o; o >>= 1) s += __shfl_xor_sync(0xffffffffu, s, o);
    __syncthreads();
    if ((tid & 31) == 0) red[tid >> 5] = s;
    __syncthreads();
    if (tid == 0) {
        float tot = 0.f;
        #pragma unroll
        for (int i = 0; i < 8; i++) tot += red[i];
        *q = tot;
    }
}

// ---------------- P2: pairwise dot products (one warp per dot) -------------
__global__ void k_dots() {
    int w    = (blockIdx.x * blockDim.x + threadIdx.x) >> 5;
    int lane = threadIdx.x & 31;
    const float *a, *b;
    float* dst;
    if (w < 2048) {
        int i = w >> 7, j = w & 127;
        a = g_cx + i * DD; b = g_ct + j * DD; dst = g_dxt + w;
    } else if (w < 4096) {
        int w2 = w - 2048;
        int i = w2 >> 7, j = w2 & 127;
        a = g_cx + i * DD; b = g_cf + j * DD; dst = g_dxf + w2;
    } else {
        int w3 = w - 4096;
        a = g_ct + (w3 >> 7) * DD; b = g_cf + (w3 & 127) * DD; dst = g_dtf + w3;
    }
    const float4* a4 = (const float4*)a;
    const float4* b4 = (const float4*)b;
    float s = 0.f;
    #pragma unroll
    for (int j = 0; j < 2; j++) {
        float4 av = a4[lane * 2 + j];
        float4 bv = b4[lane * 2 + j];
        s += av.x * bv.x + av.y * bv.y + av.z * bv.z + av.w * bv.w;
    }
    #pragma unroll
    for (int o = 16; o; o >>= 1) s += __shfl_xor_sync(0xffffffffu, s, o);
    if (lane == 0) *dst = s;
}

// ---------------- P3: 4 rows/block through W1 (one W1 stream per block) ----
__global__ void k_project(const float* __restrict__ ln_g,
                          const float* __restrict__ ln_b,
                          const float* __restrict__ W1,
                          const float* __restrict__ b1) {
    __shared__ float4 cg[DD];   // [k] -> (row0..row3)
    int r0 = blockIdx.x * 4;
    int e = threadIdx.x;        // 512 threads

    if (e < DD) {
        float g = ln_g[e];
        float4 v;
        float* vp = (float*)&v;
        #pragma unroll
        for (int j = 0; j < 4; j++) {
            int r = r0 + j;
            float c;
            if (r < 16)        c = g_cx[r * DD + e] * g;
            else if (r < 144)  c = g_ct[(r - 16) * DD + e] * g;
            else if (r < 272)  c = g_cf[(r - 144) * DD + e] * g;
            else if (r == 272) c = ln_b[e];
            else               c = 0.f;
            vp[j] = c;
        }
        cg[e] = v;
    }
    __syncthreads();

    float a0 = 0.f, a1 = 0.f, a2 = 0.f, a3 = 0.f;
    #pragma unroll 4
    for (int k = 0; k < DD; k++) {
        float w = W1[k * E2 + e];
        float4 v = cg[k];
        a0 = fmaf(v.x, w, a0);
        a1 = fmaf(v.y, w, a1);
        a2 = fmaf(v.z, w, a2);
        a3 = fmaf(v.w, w, a3);
    }
    float acc[4] = {a0, a1, a2, a3};
    #pragma unroll
    for (int j = 0; j < 4; j++) {
        int r = r0 + j;
        if (r < 16)        g_ux[r * E2 + e] = acc[j];
        else if (r < 144)  g_ut[(r - 16) * E2 + e] = acc[j];
        else if (r < 272)  g_uf[(r - 144) * E2 + e] = acc[j];
        else if (r == 272) g_c[e] = acc[j] + b1[e];
    }
}

// ---------------- main: 16 combos/thread, packed f32x2 math ----------------
// block: (4t, 16bn, 16f) tile, 128 threads = 2 e-halves x 64 threads.
// thread: ti in [0,4), bn in {bng, bng+8}, f in {f0+fg, f0+fg+8}.
__global__ void __launch_bounds__(128, 2)
k_main(const float* __restrict__ W2, const float* __restrict__ b2,
       float* __restrict__ out) {
    extern __shared__ float sm[];
    float* s_ut = sm;                  // 4  rows x SROW
    float* s_uf = sm + 4 * SROW;       // 16 rows
    float* s_ux = sm + 20 * SROW;      // 16 rows
    float* s_c  = sm + 36 * SROW;      // 512
    float* s_w0 = s_c + E2;            // 512
    float* s_w1 = s_w0 + E2;           // 512

    int t0 = blockIdx.x * 4;
    int f0 = blockIdx.y * 16;
    int tid = threadIdx.x;

    // fill smem (coalesced global reads, conflict-free writes)
    for (int i = tid; i < 36 * E2; i += 128) {
        int r = i >> 9, e = i & 511;
        float v;
        if (r < 4)       v = g_ut[(t0 + r) * E2 + e];
        else if (r < 20) v = g_uf[(f0 + r - 4) * E2 + e];
        else             v = g_ux[(r - 20) * E2 + e];
        sm[r * SROW + e] = v;
    }
    for (int i = tid; i < E2; i += 128) {
        s_c[i]  = g_c[i];
        s_w0[i] = W2[2 * i];
        s_w1[i] = W2[2 * i + 1];
    }

    int eh  = tid >> 6;
    int sub = tid & 63;
    int bng = sub >> 3;     // 0..7
    int fg  = sub & 7;      // 0..7

    // per-combo rinv (packed), from decomposed variance terms
    u64 rinv2[16];
    #pragma unroll
    for (int ti = 0; ti < 4; ti++) {
        int t = t0 + ti;
        float qt = g_qt[t];
        #pragma unroll
        for (int fi = 0; fi < 2; fi++) {
            int f = f0 + fg + fi * 8;
            float qtf = qt + g_qf[f] + 2.0f * g_dtf[t * 128 + f];
            #pragma unroll
            for (int bi = 0; bi < 2; bi++) {
                int bn = bng + bi * 8;
                float var = (qtf + g_qx[bn]
                             + 2.0f * (g_dxt[bn * 128 + t] + g_dxf[bn * 128 + f]))
                            * (1.0f / 256.0f);
                rinv2[ti * 4 + fi * 2 + bi] = pack2(rsqrtf(var + EPS));
            }
        }
    }
    __syncthreads();

    const ulonglong2* put[4];
    const ulonglong2* puf[2];
    const ulonglong2* pux[2];
    #pragma unroll
    for (int ti = 0; ti < 4; ti++)
        put[ti] = (const ulonglong2*)(s_ut + ti * SROW) + eh * 64;
    #pragma unroll
    for (int fi = 0; fi < 2; fi++)
        puf[fi] = (const ulonglong2*)(s_uf + (fg + fi * 8) * SROW) + eh * 64;
    #pragma unroll
    for (int bi = 0; bi < 2; bi++)
        pux[bi] = (const ulonglong2*)(s_ux + (bng + bi * 8) * SROW) + eh * 64;
    const ulonglong2* pc  = (const ulonglong2*)s_c  + eh * 64;
    const ulonglong2* pw0 = (const ulonglong2*)s_w0 + eh * 64;
    const ulonglong2* pw1 = (const ulonglong2*)s_w1 + eh * 64;

    u64 a0[16], a1[16];
    #pragma unroll
    for (int k = 0; k < 16; k++) { a0[k] = 0ull; a1[k] = 0ull; }

    #pragma unroll 2
    for (int i = 0; i < 64; i++) {
        ulonglong2 UT[4], UF[2], UX[2], C, V0, V1;
        #pragma unroll
        for (int x = 0; x < 4; x++) UT[x] = put[x][i];
        #pragma unroll
        for (int x = 0; x < 2; x++) { UF[x] = puf[x][i]; UX[x] = pux[x][i]; }
        C  = pc[i];
        V0 = pw0[i];
        V1 = pw1[i];

        #pragma unroll
        for (int ti = 0; ti < 4; ti++) {
            #pragma unroll
            for (int fi = 0; fi < 2; fi++) {
                u64 p0 = add2(UT[ti].x, UF[fi].x);
                u64 p1 = add2(UT[ti].y, UF[fi].y);
                #pragma unroll
                for (int bi = 0; bi < 2; bi++) {
                    int k = ti * 4 + fi * 2 + bi;
                    u64 z0 = relu2(fma2(rinv2[k], add2(p0, UX[bi].x), C.x));
                    u64 z1 = relu2(fma2(rinv2[k], add2(p1, UX[bi].y), C.y));
                    a0[k] = fma2(z0, V0.x, a0[k]);
                    a0[k] = fma2(z1, V0.y, a0[k]);
                    a1[k] = fma2(z0, V1.x, a1[k]);
                    a1[k] = fma2(z1, V1.y, a1[k]);
                }
            }
        }
    }

    // reduce packed halves, merge the two e-halves via smem, store
    float r0[16], r1[16];
    #pragma unroll
    for (int k = 0; k < 16; k++) { r0[k] = sum2(a0[k]); r1[k] = sum2(a1[k]); }

    __syncthreads();                 // everyone done with smem streams
    float* mrg = sm;                 // alias (32 x 64 floats = 8KB)
    if (eh == 1) {
        #pragma unroll
        for (int k = 0; k < 16; k++) {
            mrg[(2 * k)     * 64 + sub] = r0[k];
            mrg[(2 * k + 1) * 64 + sub] = r1[k];
        }
    }
    __syncthreads();
    if (eh == 0) {
        float b20 = b2[0], b21 = b2[1];
        #pragma unroll
        for (int ti = 0; ti < 4; ti++) {
            #pragma unroll
            for (int fi = 0; fi < 2; fi++) {
                #pragma unroll
                for (int bi = 0; bi < 2; bi++) {
                    int k = ti * 4 + fi * 2 + bi;
                    float o0 = r0[k] + mrg[(2 * k)     * 64 + sub] + b20;
                    float o1 = r1[k] + mrg[(2 * k + 1) * 64 + sub] + b21;
                    int t  = t0 + ti;
                    int f  = f0 + fg + fi * 8;
                    int bn = bng + bi * 8;
                    ((float2*)out)[(bn * NT + t) * NF + f] = make_float2(o0, o1);
                }
            }
        }
    }
}

// ---------------- launch ----------------------------------------------------
extern "C" void kernel_launch(void* const* d_in, const int* in_sizes, int n_in,
                              void* d_out, int out_size) {
    const float* x     = (const float*)d_in[0];
    const float* t_emb = (const float*)d_in[1];
    const float* f_emb = (const float*)d_in[2];
    const float* ln_g  = (const float*)d_in[3];
    const float* ln_b  = (const float*)d_in[4];
    const float* W1    = (const float*)d_in[5];
    const float* b1    = (const float*)d_in[6];
    const float* W2    = (const float*)d_in[7];
    const float* b2    = (const float*)d_in[8];
    float* out = (float*)d_out;

    const int smem_bytes = (36 * SROW + 3 * E2) * (int)sizeof(float);  // 80448
    cudaFuncSetAttribute(k_main, cudaFuncAttributeMaxDynamicSharedMemorySize, smem_bytes);

    k_center<<<272, 256>>>(x, t_emb, f_emb);
    k_dots<<<2560, 256>>>();
    k_project<<<69, 512>>>(ln_g, ln_b, W1, b1);
    dim3 grid(32, 8);
    k_main<<<grid, 128, smem_bytes>>>(W2, b2, out);
}

// round 3
// speedup vs baseline: 1.5234x; 1.5234x over previous
#include <cuda_runtime.h>

#define DD   256
#define E2   512
#define NT   128
#define NF   128
#define NBN  16
#define SROW 516
#define EPS  1e-5f

typedef unsigned long long u64;

// ---------------- packed f32x2 helpers (Blackwell 2xFP32) ------------------
__device__ __forceinline__ u64 add2(u64 a, u64 b) {
    u64 d; asm("add.rn.f32x2 %0,%1,%2;" : "=l"(d) : "l"(a), "l"(b)); return d;
}
__device__ __forceinline__ u64 fma2(u64 a, u64 b, u64 c) {
    u64 d; asm("fma.rn.f32x2 %0,%1,%2,%3;" : "=l"(d) : "l"(a), "l"(b), "l"(c)); return d;
}
__device__ __forceinline__ u64 relu2(u64 a) {
    u64 d;
    asm("{\n\t.reg .f32 l,h;\n\tmov.b64 {l,h}, %1;\n\t"
        "max.f32 l, l, 0f00000000;\n\tmax.f32 h, h, 0f00000000;\n\t"
        "mov.b64 %0, {l,h};\n\t}" : "=l"(d) : "l"(a));
    return d;
}
__device__ __forceinline__ float sum2(u64 a) {
    float l, h; asm("mov.b64 {%0,%1}, %2;" : "=f"(l), "=f"(h) : "l"(a)); return l + h;
}
__device__ __forceinline__ u64 pack2(float v) {
    u64 d; asm("mov.b64 %0, {%1,%1};" : "=l"(d) : "f"(v)); return d;
}

// ---------------- scratch (device globals; no allocation allowed) ----------
__device__ float g_cx[NBN * DD];
__device__ float g_ct[NT * DD];
__device__ float g_cf[NF * DD];
__device__ float g_qx[NBN];
__device__ float g_qt[NT];
__device__ float g_qf[NF];
__device__ float g_dxt[NBN * NT];
__device__ float g_dxf[NBN * NF];
__device__ float g_dtf[NT * NF];
__device__ float g_ux[NBN * E2];
__device__ float g_ut[NT * E2];
__device__ float g_uf[NF * E2];
__device__ float g_c[E2];

// ---------------- P1: center each embedding row, store centered + sq-norm --
__global__ void k_center(const float* __restrict__ x,
                         const float* __restrict__ t_emb,
                         const float* __restrict__ f_emb) {
    __shared__ float red[8];
    __shared__ float s_mu;
    int r = blockIdx.x;
    const float* src;
    float* dst;
    float* q;
    if (r < 16)       { src = x + r * DD;            dst = g_cx + r * DD;        q = g_qx + r; }
    else if (r < 144) { int i = r - 16;  src = t_emb + i * DD; dst = g_ct + i * DD; q = g_qt + i; }
    else              { int i = r - 144; src = f_emb + i * DD; dst = g_cf + i * DD; q = g_qf + i; }

    int tid = threadIdx.x;
    float v = src[tid];

    float s = v;
    #pragma unroll
    for (int o = 16; o; o >>= 1) s += __shfl_xor_sync(0xffffffffu, s, o);
    if ((tid & 31) == 0) red[tid >> 5] = s;
    __syncthreads();
    if (tid == 0) {
        float tot = 0.f;
        #pragma unroll
        for (int i = 0; i < 8; i++) tot += red[i];
        s_mu = tot * (1.0f / DD);
    }
    __syncthreads();

    float c = v - s_mu;
    dst[tid] = c;

    s = c * c;
    #pragma unroll
    for (int o = 16; o; o >>= 1) s += __shfl_xor_sync(0xffffffffu, s, o);
    __syncthreads();
    if ((tid & 31) == 0) red[tid >> 5] = s;
    __syncthreads();
    if (tid == 0) {
        float tot = 0.f;
        #pragma unroll
        for (int i = 0; i < 8; i++) tot += red[i];
        *q = tot;
    }
}

// ---------------- P2: pairwise dot products (one warp per dot) -------------
__global__ void k_dots() {
    int w    = (blockIdx.x * blockDim.x + threadIdx.x) >> 5;
    int lane = threadIdx.x & 31;
    const float *a, *b;
    float* dst;
    if (w < 2048) {
        int i = w >> 7, j = w & 127;
        a = g_cx + i * DD; b = g_ct + j * DD; dst = g_dxt + w;
    } else if (w < 4096) {
        int w2 = w - 2048;
        int i = w2 >> 7, j = w2 & 127;
        a = g_cx + i * DD; b = g_cf + j * DD; dst = g_dxf + w2;
    } else {
        int w3 = w - 4096;
        a = g_ct + (w3 >> 7) * DD; b = g_cf + (w3 & 127) * DD; dst = g_dtf + w3;
    }
    const float4* a4 = (const float4*)a;
    const float4* b4 = (const float4*)b;
    float s = 0.f;
    #pragma unroll
    for (int j = 0; j < 2; j++) {
        float4 av = a4[lane * 2 + j];
        float4 bv = b4[lane * 2 + j];
        s += av.x * bv.x + av.y * bv.y + av.z * bv.z + av.w * bv.w;
    }
    #pragma unroll
    for (int o = 16; o; o >>= 1) s += __shfl_xor_sync(0xffffffffu, s, o);
    if (lane == 0) *dst = s;
}

// ---------------- P3: 4 rows/block through W1 (one W1 stream per block) ----
__global__ void k_project(const float* __restrict__ ln_g,
                          const float* __restrict__ ln_b,
                          const float* __restrict__ W1,
                          const float* __restrict__ b1) {
    __shared__ float4 cg[DD];   // [k] -> (row0..row3)
    int r0 = blockIdx.x * 4;
    int e = threadIdx.x;        // 512 threads

    if (e < DD) {
        float g = ln_g[e];
        float4 v;
        float* vp = (float*)&v;
        #pragma unroll
        for (int j = 0; j < 4; j++) {
            int r = r0 + j;
            float c;
            if (r < 16)        c = g_cx[r * DD + e] * g;
            else if (r < 144)  c = g_ct[(r - 16) * DD + e] * g;
            else if (r < 272)  c = g_cf[(r - 144) * DD + e] * g;
            else if (r == 272) c = ln_b[e];
            else               c = 0.f;
            vp[j] = c;
        }
        cg[e] = v;
    }
    __syncthreads();

    float a0 = 0.f, a1 = 0.f, a2 = 0.f, a3 = 0.f;
    #pragma unroll 4
    for (int k = 0; k < DD; k++) {
        float w = W1[k * E2 + e];
        float4 v = cg[k];
        a0 = fmaf(v.x, w, a0);
        a1 = fmaf(v.y, w, a1);
        a2 = fmaf(v.z, w, a2);
        a3 = fmaf(v.w, w, a3);
    }
    float acc[4] = {a0, a1, a2, a3};
    #pragma unroll
    for (int j = 0; j < 4; j++) {
        int r = r0 + j;
        if (r < 16)        g_ux[r * E2 + e] = acc[j];
        else if (r < 144)  g_ut[(r - 16) * E2 + e] = acc[j];
        else if (r < 272)  g_uf[(r - 144) * E2 + e] = acc[j];
        else if (r == 272) g_c[e] = acc[j] + b1[e];
    }
}

// ---------------- main: 2bn x 2f per thread, e split 4 ways, f32x2 math ----
// grid (t=128, fb=8); block 256 = 4 e-quarters x (8 fg x 4 bng... lane = cg).
// thread: combos (bn in {bng, bng+8}) x (f in {f0+fg, f0+fg+8}), e-quarter eq.
__global__ void __launch_bounds__(256, 3)
k_main(const float* __restrict__ W2, const float* __restrict__ b2,
       float* __restrict__ out) {
    extern __shared__ float sm[];
    float* s_tf = sm;                  // [16][SROW]: ut[t] + uf[f0+r]
    float* s_ux = sm + 16 * SROW;      // [16][SROW]
    float* s_c  = sm + 32 * SROW;      // [512]
    float* s_w0 = s_c + E2;            // [512]
    float* s_w1 = s_w0 + E2;           // [512]

    int t   = blockIdx.x;
    int f0  = blockIdx.y * 16;
    int tid = threadIdx.x;

    // fill smem with float4 (coalesced, conflict-free)
    {
        const float4* ut4 = (const float4*)(g_ut + t * E2);
        for (int i = tid; i < 16 * 128; i += 256) {
            int r = i >> 7, e4 = i & 127;
            float4 a = ut4[e4];
            float4 b = ((const float4*)(g_uf + (f0 + r) * E2))[e4];
            ((float4*)(s_tf + r * SROW))[e4] =
                make_float4(a.x + b.x, a.y + b.y, a.z + b.z, a.w + b.w);
            ((float4*)(s_ux + r * SROW))[e4] = ((const float4*)(g_ux + r * E2))[e4];
        }
        for (int i = tid; i < E2; i += 256) {
            s_c[i]  = g_c[i];
            s_w0[i] = W2[2 * i];
            s_w1[i] = W2[2 * i + 1];
        }
    }

    int eq  = tid >> 6;     // e-quarter 0..3
    int cg  = tid & 63;     // combo group
    int bng = cg >> 3;      // 0..7
    int fg  = cg & 7;       // 0..7

    // per-combo rinv (packed), from decomposed variance terms
    u64 rinv2[4];
    float qt = g_qt[t];
    #pragma unroll
    for (int fi = 0; fi < 2; fi++) {
        int f = f0 + fg + fi * 8;
        float qtf = qt + g_qf[f] + 2.0f * g_dtf[t * 128 + f];
        #pragma unroll
        for (int bi = 0; bi < 2; bi++) {
            int bn = bng + bi * 8;
            float var = (qtf + g_qx[bn]
                         + 2.0f * (g_dxt[bn * 128 + t] + g_dxf[bn * 128 + f]))
                        * (1.0f / 256.0f);
            rinv2[fi * 2 + bi] = pack2(rsqrtf(var + EPS));
        }
    }
    __syncthreads();

    const ulonglong2* ptf0 = (const ulonglong2*)(s_tf + fg * SROW) + eq * 32;
    const ulonglong2* ptf1 = (const ulonglong2*)(s_tf + (fg + 8) * SROW) + eq * 32;
    const ulonglong2* pux0 = (const ulonglong2*)(s_ux + bng * SROW) + eq * 32;
    const ulonglong2* pux1 = (const ulonglong2*)(s_ux + (bng + 8) * SROW) + eq * 32;
    const ulonglong2* pc   = (const ulonglong2*)s_c  + eq * 32;
    const ulonglong2* pw0  = (const ulonglong2*)s_w0 + eq * 32;
    const ulonglong2* pw1  = (const ulonglong2*)s_w1 + eq * 32;

    u64 a0[4], a1[4];
    #pragma unroll
    for (int k = 0; k < 4; k++) { a0[k] = 0ull; a1[k] = 0ull; }

    #pragma unroll 4
    for (int i = 0; i < 32; i++) {
        ulonglong2 TF0 = ptf0[i], TF1 = ptf1[i];
        ulonglong2 UX0 = pux0[i], UX1 = pux1[i];
        ulonglong2 C = pc[i], V0 = pw0[i], V1 = pw1[i];

        #pragma unroll
        for (int fi = 0; fi < 2; fi++) {
            ulonglong2 TF = fi ? TF1 : TF0;
            #pragma unroll
            for (int bi = 0; bi < 2; bi++) {
                ulonglong2 UX = bi ? UX1 : UX0;
                int k = fi * 2 + bi;
                u64 z0 = relu2(fma2(rinv2[k], add2(TF.x, UX.x), C.x));
                u64 z1 = relu2(fma2(rinv2[k], add2(TF.y, UX.y), C.y));
                a0[k] = fma2(z0, V0.x, a0[k]);
                a0[k] = fma2(z1, V0.y, a0[k]);
                a1[k] = fma2(z0, V1.x, a1[k]);
                a1[k] = fma2(z1, V1.y, a1[k]);
            }
        }
    }

    // reduce packed halves, merge 4 e-quarter partials via smem, store
    float r0[4], r1[4];
    #pragma unroll
    for (int k = 0; k < 4; k++) { r0[k] = sum2(a0[k]); r1[k] = sum2(a1[k]); }

    __syncthreads();                 // all smem-stream reads done
    float* mrg = sm;                 // alias: [ (k*2+o)*4 + eq ][ cg ] -> 2048 floats
    #pragma unroll
    for (int k = 0; k < 4; k++) {
        mrg[((k * 2 + 0) * 4 + eq) * 64 + cg] = r0[k];
        mrg[((k * 2 + 1) * 4 + eq) * 64 + cg] = r1[k];
    }
    __syncthreads();

    if (eq == 0) {
        float b20 = b2[0], b21 = b2[1];
        #pragma unroll
        for (int fi = 0; fi < 2; fi++) {
            #pragma unroll
            for (int bi = 0; bi < 2; bi++) {
                int k = fi * 2 + bi;
                float o0 = b20, o1 = b21;
                #pragma unroll
                for (int q = 0; q < 4; q++) {
                    o0 += mrg[((k * 2 + 0) * 4 + q) * 64 + cg];
                    o1 += mrg[((k * 2 + 1) * 4 + q) * 64 + cg];
                }
                int f  = f0 + fg + fi * 8;
                int bn = bng + bi * 8;
                ((float2*)out)[(bn * NT + t) * NF + f] = make_float2(o0, o1);
            }
        }
    }
}

// ---------------- launch ----------------------------------------------------
extern "C" void kernel_launch(void* const* d_in, const int* in_sizes, int n_in,
                              void* d_out, int out_size) {
    const float* x     = (const float*)d_in[0];
    const float* t_emb = (const float*)d_in[1];
    const float* f_emb = (const float*)d_in[2];
    const float* ln_g  = (const float*)d_in[3];
    const float* ln_b  = (const float*)d_in[4];
    const float* W1    = (const float*)d_in[5];
    const float* b1    = (const float*)d_in[6];
    const float* W2    = (const float*)d_in[7];
    const float* b2    = (const float*)d_in[8];
    float* out = (float*)d_out;

    const int smem_bytes = (32 * SROW + 3 * E2) * (int)sizeof(float);  // 72192
    cudaFuncSetAttribute(k_main, cudaFuncAttributeMaxDynamicSharedMemorySize, smem_bytes);

    k_center<<<272, 256>>>(x, t_emb, f_emb);
    k_dots<<<2560, 256>>>();
    k_project<<<69, 512>>>(ln_g, ln_b, W1, b1);
    dim3 grid(NT, 8);
    k_main<<<grid, 256, smem_bytes>>>(W2, b2, out);
}